// round 1
// baseline (speedup 1.0000x reference)
#include <cuda_runtime.h>
#include <cstdint>

// Problem constants
#define BS      2
#define TT      8
#define NOBJ    4
#define CH      64
#define CH2     32     // CH/2
#define DIM     64
#define NN      1024   // W*H
#define BTO     64     // BS*NOBJ*TT
#define KBN     16     // BS*TT unique K/V batches

// Scratch (device globals; no allocation allowed)
__device__ float g_Q[BTO * CH2 * NN];   // [b][o][n]   8 MB
__device__ float g_K[KBN * CH2 * NN];   // [kb][o][m]  2 MB
__device__ float g_V[KBN * DIM * NN];   // [kb][d][c]  4 MB

// ---------------------------------------------------------------------------
// Kernel 1: QKV projections. grid=64 (one per b), block=256, 4 n per thread.
// K/V computed only by obj==0 blocks (16 unique kb).
// ---------------------------------------------------------------------------
__global__ void __launch_bounds__(256) qkv_kernel(
    const float* __restrict__ inp,   // [BS*TT][CH][NN]
    const float* __restrict__ dyn,   // [BTO][CH][NN]
    const float* __restrict__ wq, const float* __restrict__ bq,
    const float* __restrict__ wk, const float* __restrict__ bk,
    const float* __restrict__ wv, const float* __restrict__ bv)
{
    __shared__ float swq[CH2 * CH];
    __shared__ float swk[CH2 * CH];
    __shared__ float swv[DIM * CH];

    const int tid = threadIdx.x;
    const int b   = blockIdx.x;
    const int t   = b & 7;
    const int obj = (b >> 3) & 3;
    const int bi  = b >> 5;
    const int kb  = bi * TT + t;

    for (int i = tid; i < CH2 * CH; i += 256) { swq[i] = wq[i]; swk[i] = wk[i]; }
    for (int i = tid; i < DIM * CH; i += 256) swv[i] = wv[i];
    __syncthreads();

    const float* xd = dyn + (size_t)b  * CH * NN;
    const float* xi = inp + (size_t)kb * CH * NN;

    // ---- Q = Wq @ Xdyn + bq, stored [b][o][n] ----
    {
        float4 acc[CH2];
        #pragma unroll
        for (int o = 0; o < CH2; o++) acc[o] = make_float4(0.f, 0.f, 0.f, 0.f);
        for (int c = 0; c < CH; c++) {
            const float x0 = xd[c * NN + tid];
            const float x1 = xd[c * NN + tid + 256];
            const float x2 = xd[c * NN + tid + 512];
            const float x3 = xd[c * NN + tid + 768];
            #pragma unroll
            for (int o = 0; o < CH2; o++) {
                const float w = swq[(o << 6) + c];
                acc[o].x = fmaf(w, x0, acc[o].x);
                acc[o].y = fmaf(w, x1, acc[o].y);
                acc[o].z = fmaf(w, x2, acc[o].z);
                acc[o].w = fmaf(w, x3, acc[o].w);
            }
        }
        float* Qb = g_Q + (size_t)b * CH2 * NN;
        #pragma unroll
        for (int o = 0; o < CH2; o++) {
            const float bb = bq[o];
            Qb[o * NN + tid      ] = acc[o].x + bb;
            Qb[o * NN + tid + 256] = acc[o].y + bb;
            Qb[o * NN + tid + 512] = acc[o].z + bb;
            Qb[o * NN + tid + 768] = acc[o].w + bb;
        }
    }

    if (obj != 0) return;

    // ---- K = Wk @ Xin + bk, stored [kb][o][m] ----
    {
        float4 acc[CH2];
        #pragma unroll
        for (int o = 0; o < CH2; o++) acc[o] = make_float4(0.f, 0.f, 0.f, 0.f);
        for (int c = 0; c < CH; c++) {
            const float x0 = xi[c * NN + tid];
            const float x1 = xi[c * NN + tid + 256];
            const float x2 = xi[c * NN + tid + 512];
            const float x3 = xi[c * NN + tid + 768];
            #pragma unroll
            for (int o = 0; o < CH2; o++) {
                const float w = swk[(o << 6) + c];
                acc[o].x = fmaf(w, x0, acc[o].x);
                acc[o].y = fmaf(w, x1, acc[o].y);
                acc[o].z = fmaf(w, x2, acc[o].z);
                acc[o].w = fmaf(w, x3, acc[o].w);
            }
        }
        float* Kb = g_K + (size_t)kb * CH2 * NN;
        #pragma unroll
        for (int o = 0; o < CH2; o++) {
            const float bb = bk[o];
            Kb[o * NN + tid      ] = acc[o].x + bb;
            Kb[o * NN + tid + 256] = acc[o].y + bb;
            Kb[o * NN + tid + 512] = acc[o].z + bb;
            Kb[o * NN + tid + 768] = acc[o].w + bb;
        }
    }

    // ---- V = Wv @ Xin + bv, stored [kb][d][c] (two halves of 32 d) ----
    for (int h = 0; h < 2; h++) {
        float4 acc[32];
        #pragma unroll
        for (int o = 0; o < 32; o++) acc[o] = make_float4(0.f, 0.f, 0.f, 0.f);
        for (int c = 0; c < CH; c++) {
            const float x0 = xi[c * NN + tid];
            const float x1 = xi[c * NN + tid + 256];
            const float x2 = xi[c * NN + tid + 512];
            const float x3 = xi[c * NN + tid + 768];
            #pragma unroll
            for (int o = 0; o < 32; o++) {
                const float w = swv[((h * 32 + o) << 6) + c];
                acc[o].x = fmaf(w, x0, acc[o].x);
                acc[o].y = fmaf(w, x1, acc[o].y);
                acc[o].z = fmaf(w, x2, acc[o].z);
                acc[o].w = fmaf(w, x3, acc[o].w);
            }
        }
        float* Vb = g_V + (size_t)kb * DIM * NN;
        #pragma unroll
        for (int o = 0; o < 32; o++) {
            const int d = h * 32 + o;
            const float bb = bv[d];
            Vb[d * NN + tid      ] = acc[o].x + bb;
            Vb[d * NN + tid + 256] = acc[o].y + bb;
            Vb[d * NN + tid + 512] = acc[o].z + bb;
            Vb[d * NN + tid + 768] = acc[o].w + bb;
        }
    }
}

// ---------------------------------------------------------------------------
// Kernel 2: energy + softmax -> attn.  grid=(32 rowtiles, 64 b), block=512.
// K[b] (32x1024 fp32, 128KB) resident in smem; warp computes 2 full rows with
// the energy row held in registers (32 floats/lane) -> softmax in-register.
// ---------------------------------------------------------------------------
extern __shared__ float s_dyn[];

__global__ void __launch_bounds__(512) attn_kernel(float* __restrict__ attn_out)
{
    float* ks = s_dyn;                 // [32][1024]
    float* qs = s_dyn + CH2 * NN;      // [o][r] 32x32

    const int tid  = threadIdx.x;
    const int b    = blockIdx.y;
    const int r0   = blockIdx.x * 32;
    const int t    = b & 7;
    const int bi   = b >> 5;
    const int kb   = bi * TT + t;

    // load K[kb] into smem
    {
        const float4* kg = (const float4*)(g_K + (size_t)kb * CH2 * NN);
        float4* kw = (float4*)ks;
        #pragma unroll
        for (int i = tid; i < CH2 * NN / 4; i += 512) kw[i] = kg[i];
    }
    // load Q tile [32 o][32 r]
    {
        const float* Qb = g_Q + (size_t)b * CH2 * NN;
        for (int i = tid; i < 1024; i += 512) {
            const int o = i >> 5, r = i & 31;
            qs[i] = Qb[o * NN + r0 + r];
        }
    }
    __syncthreads();

    const int warp = tid >> 5, lane = tid & 31;
    const int rl = warp * 2;               // local rows rl, rl+1

    float4 accA[8], accB[8];
    #pragma unroll
    for (int j = 0; j < 8; j++) { accA[j] = make_float4(0,0,0,0); accB[j] = make_float4(0,0,0,0); }

    const float4* ks4 = (const float4*)ks;
    #pragma unroll 4
    for (int o = 0; o < CH2; o++) {
        const float qa = qs[o * 32 + rl];
        const float qb = qs[o * 32 + rl + 1];
        const int base = o * 256 + lane;
        #pragma unroll
        for (int j = 0; j < 8; j++) {
            const float4 kv = ks4[base + 32 * j];
            accA[j].x = fmaf(qa, kv.x, accA[j].x);
            accA[j].y = fmaf(qa, kv.y, accA[j].y);
            accA[j].z = fmaf(qa, kv.z, accA[j].z);
            accA[j].w = fmaf(qa, kv.w, accA[j].w);
            accB[j].x = fmaf(qb, kv.x, accB[j].x);
            accB[j].y = fmaf(qb, kv.y, accB[j].y);
            accB[j].z = fmaf(qb, kv.z, accB[j].z);
            accB[j].w = fmaf(qb, kv.w, accB[j].w);
        }
    }

    // softmax + store for each of the two rows
    #pragma unroll
    for (int rr = 0; rr < 2; rr++) {
        float4* acc = (rr == 0) ? accA : accB;
        float m = -3.4e38f;
        #pragma unroll
        for (int j = 0; j < 8; j++) {
            m = fmaxf(m, fmaxf(fmaxf(acc[j].x, acc[j].y), fmaxf(acc[j].z, acc[j].w)));
        }
        #pragma unroll
        for (int off = 16; off > 0; off >>= 1)
            m = fmaxf(m, __shfl_xor_sync(0xffffffffu, m, off));
        float s = 0.f;
        #pragma unroll
        for (int j = 0; j < 8; j++) {
            acc[j].x = __expf(acc[j].x - m);
            acc[j].y = __expf(acc[j].y - m);
            acc[j].z = __expf(acc[j].z - m);
            acc[j].w = __expf(acc[j].w - m);
            s += acc[j].x + acc[j].y + acc[j].z + acc[j].w;
        }
        #pragma unroll
        for (int off = 16; off > 0; off >>= 1)
            s += __shfl_xor_sync(0xffffffffu, s, off);
        const float inv = 1.f / s;
        const int row = r0 + rl + rr;
        float4* dst = (float4*)(attn_out + ((size_t)b * NN + row) * NN);
        #pragma unroll
        for (int j = 0; j < 8; j++) {
            float4 p = acc[j];
            p.x *= inv; p.y *= inv; p.z *= inv; p.w *= inv;
            dst[lane + 32 * j] = p;
        }
    }
}

// ---------------------------------------------------------------------------
// Kernel 3: Out[b][d][r] = sum_c V[kb][d][c] * attn[b][r][c]
// grid=(16 rtiles, 64 b), block=256, 64x64 tile, 4x4 microtile.
// ---------------------------------------------------------------------------
#define PAD 68

__global__ void __launch_bounds__(256) av_kernel(
    const float* __restrict__ attn, float* __restrict__ out)
{
    __shared__ float Vs[32 * PAD];   // [c][d]
    __shared__ float As[32 * PAD];   // [c][r]

    const int tid = threadIdx.x;
    const int b   = blockIdx.y;
    const int r0  = blockIdx.x * 64;
    const int t   = b & 7;
    const int bi  = b >> 5;
    const int kb  = bi * TT + t;

    const float* Vg = g_V + (size_t)kb * DIM * NN;
    const float* Ag = attn + ((size_t)b * NN + r0) * NN;

    const int cl = tid & 31, gl = tid >> 5;        // loaders
    const int tx = tid & 15, ty = tid >> 4;        // compute mapping

    float4 acc0 = make_float4(0,0,0,0), acc1 = acc0, acc2 = acc0, acc3 = acc0;

    for (int c0 = 0; c0 < NN; c0 += 32) {
        #pragma unroll
        for (int p = 0; p < 8; p++) {
            const int dd = gl + (p << 3);
            Vs[cl * PAD + dd] = Vg[(size_t)dd * NN + c0 + cl];
            As[cl * PAD + dd] = Ag[(size_t)dd * NN + c0 + cl];
        }
        __syncthreads();
        #pragma unroll
        for (int k = 0; k < 32; k++) {
            const float4 a  = *(const float4*)&As[k * PAD + tx * 4];
            const float4 vv = *(const float4*)&Vs[k * PAD + ty * 4];
            acc0.x = fmaf(vv.x, a.x, acc0.x); acc0.y = fmaf(vv.x, a.y, acc0.y);
            acc0.z = fmaf(vv.x, a.z, acc0.z); acc0.w = fmaf(vv.x, a.w, acc0.w);
            acc1.x = fmaf(vv.y, a.x, acc1.x); acc1.y = fmaf(vv.y, a.y, acc1.y);
            acc1.z = fmaf(vv.y, a.z, acc1.z); acc1.w = fmaf(vv.y, a.w, acc1.w);
            acc2.x = fmaf(vv.z, a.x, acc2.x); acc2.y = fmaf(vv.z, a.y, acc2.y);
            acc2.z = fmaf(vv.z, a.z, acc2.z); acc2.w = fmaf(vv.z, a.w, acc2.w);
            acc3.x = fmaf(vv.w, a.x, acc3.x); acc3.y = fmaf(vv.w, a.y, acc3.y);
            acc3.z = fmaf(vv.w, a.z, acc3.z); acc3.w = fmaf(vv.w, a.w, acc3.w);
        }
        __syncthreads();
    }

    float* Ob = out + (size_t)b * DIM * NN;
    const int col = r0 + tx * 4;
    *(float4*)&Ob[(ty * 4 + 0) * NN + col] = acc0;
    *(float4*)&Ob[(ty * 4 + 1) * NN + col] = acc1;
    *(float4*)&Ob[(ty * 4 + 2) * NN + col] = acc2;
    *(float4*)&Ob[(ty * 4 + 3) * NN + col] = acc3;
}

// ---------------------------------------------------------------------------
extern "C" void kernel_launch(void* const* d_in, const int* in_sizes, int n_in,
                              void* d_out, int out_size)
{
    const float* inp = (const float*)d_in[0];
    const float* dyn = (const float*)d_in[1];
    const float* wq  = (const float*)d_in[2];
    const float* bq  = (const float*)d_in[3];
    const float* wk  = (const float*)d_in[4];
    const float* bk  = (const float*)d_in[5];
    const float* wv  = (const float*)d_in[6];
    const float* bv  = (const float*)d_in[7];

    float* out  = (float*)d_out;
    float* attn = out + (size_t)BTO * DIM * NN;   // tuple packing: out first, then attn

    const int smemB = (CH2 * NN + 1024) * sizeof(float);  // 132 KB
    static bool attr_done = false;
    if (!attr_done) {
        cudaFuncSetAttribute(attn_kernel, cudaFuncAttributeMaxDynamicSharedMemorySize, smemB);
        attr_done = true;
    }

    qkv_kernel<<<BTO, 256>>>(inp, dyn, wq, bq, wk, bk, wv, bv);
    attn_kernel<<<dim3(32, BTO), 512, smemB>>>(attn);
    av_kernel<<<dim3(16, BTO), 256>>>(attn, out);
}

// round 2
// speedup vs baseline: 1.6337x; 1.6337x over previous
#include <cuda_runtime.h>
#include <cstdint>

// Problem constants
#define BS      2
#define TT      8
#define NOBJ    4
#define CH      64
#define CH2     32
#define DIM     64
#define NN      1024
#define BTO     64
#define KBN     16

// Scratch (device globals)
__device__ float g_Q[BTO * CH2 * NN];   // [b][o][n]
__device__ float g_K[KBN * CH2 * NN];   // [kb][o][m]
__device__ float g_V[KBN * DIM * NN];   // [kb][d][n]

// ---------------------------------------------------------------------------
// Kernel 1: QKV projections, role-split grid.
//   blocks [0,256):   Q   b = id>>2, ntile = id&3
//   blocks [256,320): K   kb = (id-256)>>2, ntile = (id-256)&3
//   blocks [320,448): V   kb = (id-320)>>3, half=((id-320)>>2)&1, ntile=(id-320)&3
// Each block: 256 threads, 256 n positions, 32 output channels.
// ---------------------------------------------------------------------------
__global__ void __launch_bounds__(256) qkv_kernel(
    const float* __restrict__ inp,   // [KBN][CH][NN]
    const float* __restrict__ dyn,   // [BTO][CH][NN]
    const float* __restrict__ wq, const float* __restrict__ bq,
    const float* __restrict__ wk, const float* __restrict__ bk,
    const float* __restrict__ wv, const float* __restrict__ bv)
{
    __shared__ float sw[CH2 * CH];   // 32x64 weights
    __shared__ float sb[CH2];

    const int tid = threadIdx.x;
    const int bid = blockIdx.x;

    const float* X;
    const float* W;
    const float* B;
    float* OUT;
    int ntile;

    if (bid < 256) {
        const int b = bid >> 2; ntile = bid & 3;
        X = dyn + (size_t)b * CH * NN;
        W = wq; B = bq;
        OUT = g_Q + (size_t)b * CH2 * NN;
    } else if (bid < 320) {
        const int id = bid - 256;
        const int kb = id >> 2; ntile = id & 3;
        X = inp + (size_t)kb * CH * NN;
        W = wk; B = bk;
        OUT = g_K + (size_t)kb * CH2 * NN;
    } else {
        const int id = bid - 320;
        const int kb = id >> 3;
        const int half = (id >> 2) & 1;
        ntile = id & 3;
        X = inp + (size_t)kb * CH * NN;
        W = wv + half * 32 * CH; B = bv + half * 32;
        OUT = g_V + (size_t)kb * DIM * NN + (size_t)half * 32 * NN;
    }

    for (int i = tid; i < CH2 * CH; i += 256) sw[i] = W[i];
    if (tid < CH2) sb[tid] = B[tid];
    __syncthreads();

    const int n = ntile * 256 + tid;
    float acc[CH2];
    #pragma unroll
    for (int o = 0; o < CH2; o++) acc[o] = 0.f;

    #pragma unroll
    for (int c0 = 0; c0 < CH; c0 += 8) {
        float x[8];
        #pragma unroll
        for (int j = 0; j < 8; j++) x[j] = X[(c0 + j) * NN + n];
        #pragma unroll
        for (int o = 0; o < CH2; o++) {
            const float4 wa = *(const float4*)&sw[o * CH + c0];
            const float4 wb = *(const float4*)&sw[o * CH + c0 + 4];
            acc[o] = fmaf(wa.x, x[0], acc[o]);
            acc[o] = fmaf(wa.y, x[1], acc[o]);
            acc[o] = fmaf(wa.z, x[2], acc[o]);
            acc[o] = fmaf(wa.w, x[3], acc[o]);
            acc[o] = fmaf(wb.x, x[4], acc[o]);
            acc[o] = fmaf(wb.y, x[5], acc[o]);
            acc[o] = fmaf(wb.z, x[6], acc[o]);
            acc[o] = fmaf(wb.w, x[7], acc[o]);
        }
    }
    #pragma unroll
    for (int o = 0; o < CH2; o++) OUT[o * NN + n] = acc[o] + sb[o];
}

// ---------------------------------------------------------------------------
// Kernel 2: energy + softmax -> attn. grid=(32 rowtiles, 64 b), block=256.
// K[kb] (32x1024 fp32, 128KB) in smem; each of 8 warps computes 4 full rows
// in registers (FMA/byte = 1.0, FFMA-bound), softmax in-register, store.
// ---------------------------------------------------------------------------
extern __shared__ float s_dyn[];

__global__ void __launch_bounds__(256) attn_kernel(float* __restrict__ attn_out)
{
    float* ks = s_dyn;                 // [32][1024]
    float* qs = s_dyn + CH2 * NN;      // [o][r] 32x32

    const int tid = threadIdx.x;
    const int b   = blockIdx.y;
    const int r0  = blockIdx.x * 32;
    const int t   = b & 7;
    const int bi  = b >> 5;
    const int kb  = bi * TT + t;

    {
        const float4* kg = (const float4*)(g_K + (size_t)kb * CH2 * NN);
        float4* kw = (float4*)ks;
        #pragma unroll
        for (int i = tid; i < CH2 * NN / 4; i += 256) kw[i] = kg[i];
    }
    {
        const float* Qb = g_Q + (size_t)b * CH2 * NN;
        #pragma unroll
        for (int i = tid; i < 1024; i += 256) {
            const int o = i >> 5, r = i & 31;
            qs[i] = Qb[o * NN + r0 + r];
        }
    }
    __syncthreads();

    const int warp = tid >> 5, lane = tid & 31;
    const int rl = warp * 4;               // local rows rl..rl+3

    float4 acc[4][8];
    #pragma unroll
    for (int rr = 0; rr < 4; rr++)
        #pragma unroll
        for (int j = 0; j < 8; j++) acc[rr][j] = make_float4(0, 0, 0, 0);

    const float4* ks4 = (const float4*)ks;
    #pragma unroll 2
    for (int o = 0; o < CH2; o++) {
        float q[4];
        #pragma unroll
        for (int rr = 0; rr < 4; rr++) q[rr] = qs[o * 32 + rl + rr];
        const int base = o * 256 + lane;
        #pragma unroll
        for (int j = 0; j < 8; j++) {
            const float4 kv = ks4[base + 32 * j];
            #pragma unroll
            for (int rr = 0; rr < 4; rr++) {
                acc[rr][j].x = fmaf(q[rr], kv.x, acc[rr][j].x);
                acc[rr][j].y = fmaf(q[rr], kv.y, acc[rr][j].y);
                acc[rr][j].z = fmaf(q[rr], kv.z, acc[rr][j].z);
                acc[rr][j].w = fmaf(q[rr], kv.w, acc[rr][j].w);
            }
        }
    }

    #pragma unroll
    for (int rr = 0; rr < 4; rr++) {
        float m = -3.4e38f;
        #pragma unroll
        for (int j = 0; j < 8; j++)
            m = fmaxf(m, fmaxf(fmaxf(acc[rr][j].x, acc[rr][j].y),
                               fmaxf(acc[rr][j].z, acc[rr][j].w)));
        #pragma unroll
        for (int off = 16; off > 0; off >>= 1)
            m = fmaxf(m, __shfl_xor_sync(0xffffffffu, m, off));
        float s = 0.f;
        #pragma unroll
        for (int j = 0; j < 8; j++) {
            acc[rr][j].x = __expf(acc[rr][j].x - m);
            acc[rr][j].y = __expf(acc[rr][j].y - m);
            acc[rr][j].z = __expf(acc[rr][j].z - m);
            acc[rr][j].w = __expf(acc[rr][j].w - m);
            s += acc[rr][j].x + acc[rr][j].y + acc[rr][j].z + acc[rr][j].w;
        }
        #pragma unroll
        for (int off = 16; off > 0; off >>= 1)
            s += __shfl_xor_sync(0xffffffffu, s, off);
        const float inv = 1.f / s;
        const int row = r0 + rl + rr;
        float4* dst = (float4*)(attn_out + ((size_t)b * NN + row) * NN);
        #pragma unroll
        for (int j = 0; j < 8; j++) {
            float4 p = acc[rr][j];
            p.x *= inv; p.y *= inv; p.z *= inv; p.w *= inv;
            dst[lane + 32 * j] = p;
        }
    }
}

// ---------------------------------------------------------------------------
// Kernel 3: Out[b][d][m] = sum_n V[kb][d][n] * attn[b][m][n]
// grid=(4 mtiles, 64 b), block=256 (tx=tid&31, ty=tid>>5).
// Tile d=64 x m=256, k-chunk=16. 8x8 microtile as 4 conflict-free 4x4
// quadrants (16B lane stride on LDS.128).
// ---------------------------------------------------------------------------
#define PADM 260
#define PADV 68

__global__ void __launch_bounds__(256) av_kernel(
    const float* __restrict__ attn, float* __restrict__ out)
{
    __shared__ float Vs[16 * PADV];   // [k][d]
    __shared__ float As[16 * PADM];   // [k][m]

    const int tid = threadIdx.x;
    const int b   = blockIdx.y;
    const int m0  = blockIdx.x * 256;
    const int t   = b & 7;
    const int bi  = b >> 5;
    const int kb  = bi * TT + t;

    const float* Vg = g_V + (size_t)kb * DIM * NN;
    const float* Ag = attn + ((size_t)b * NN + m0) * NN;

    const int tx = tid & 31, ty = tid >> 5;
    const int lrow = tid >> 2, lnq = tid & 3;   // loader mapping

    float4 acc[2][2][4];
    #pragma unroll
    for (int db = 0; db < 2; db++)
        #pragma unroll
        for (int mb = 0; mb < 2; mb++)
            #pragma unroll
            for (int dr = 0; dr < 4; dr++) acc[db][mb][dr] = make_float4(0, 0, 0, 0);

    for (int c0 = 0; c0 < NN; c0 += 16) {
        // load V chunk: Vs[k][d], transposed from [d][n]
        {
            const float4 v = *(const float4*)&Vg[(size_t)lrow * NN + c0 + lnq * 4];
            Vs[(lnq * 4 + 0) * PADV + lrow] = v.x;
            Vs[(lnq * 4 + 1) * PADV + lrow] = v.y;
            Vs[(lnq * 4 + 2) * PADV + lrow] = v.z;
            Vs[(lnq * 4 + 3) * PADV + lrow] = v.w;
        }
        // load A chunk: As[k][m], transposed from [m][n]
        #pragma unroll
        for (int p = 0; p < 4; p++) {
            const int m = lrow + 64 * p;
            const float4 a = *(const float4*)&Ag[(size_t)m * NN + c0 + lnq * 4];
            As[(lnq * 4 + 0) * PADM + m] = a.x;
            As[(lnq * 4 + 1) * PADM + m] = a.y;
            As[(lnq * 4 + 2) * PADM + m] = a.z;
            As[(lnq * 4 + 3) * PADM + m] = a.w;
        }
        __syncthreads();

        #pragma unroll
        for (int k = 0; k < 16; k++) {
            float4 a[2], v[2];
            a[0] = *(const float4*)&As[k * PADM + tx * 4];
            a[1] = *(const float4*)&As[k * PADM + 128 + tx * 4];
            v[0] = *(const float4*)&Vs[k * PADV + ty * 4];
            v[1] = *(const float4*)&Vs[k * PADV + 32 + ty * 4];
            #pragma unroll
            for (int db = 0; db < 2; db++) {
                const float4 vv = v[db];
                #pragma unroll
                for (int mb = 0; mb < 2; mb++) {
                    const float4 aa = a[mb];
                    acc[db][mb][0].x = fmaf(vv.x, aa.x, acc[db][mb][0].x);
                    acc[db][mb][0].y = fmaf(vv.x, aa.y, acc[db][mb][0].y);
                    acc[db][mb][0].z = fmaf(vv.x, aa.z, acc[db][mb][0].z);
                    acc[db][mb][0].w = fmaf(vv.x, aa.w, acc[db][mb][0].w);
                    acc[db][mb][1].x = fmaf(vv.y, aa.x, acc[db][mb][1].x);
                    acc[db][mb][1].y = fmaf(vv.y, aa.y, acc[db][mb][1].y);
                    acc[db][mb][1].z = fmaf(vv.y, aa.z, acc[db][mb][1].z);
                    acc[db][mb][1].w = fmaf(vv.y, aa.w, acc[db][mb][1].w);
                    acc[db][mb][2].x = fmaf(vv.z, aa.x, acc[db][mb][2].x);
                    acc[db][mb][2].y = fmaf(vv.z, aa.y, acc[db][mb][2].y);
                    acc[db][mb][2].z = fmaf(vv.z, aa.z, acc[db][mb][2].z);
                    acc[db][mb][2].w = fmaf(vv.z, aa.w, acc[db][mb][2].w);
                    acc[db][mb][3].x = fmaf(vv.w, aa.x, acc[db][mb][3].x);
                    acc[db][mb][3].y = fmaf(vv.w, aa.y, acc[db][mb][3].y);
                    acc[db][mb][3].z = fmaf(vv.w, aa.z, acc[db][mb][3].z);
                    acc[db][mb][3].w = fmaf(vv.w, aa.w, acc[db][mb][3].w);
                }
            }
        }
        __syncthreads();
    }

    float* Ob = out + (size_t)b * DIM * NN;
    #pragma unroll
    for (int db = 0; db < 2; db++)
        #pragma unroll
        for (int dr = 0; dr < 4; dr++) {
            const int d = db * 32 + ty * 4 + dr;
            *(float4*)&Ob[(size_t)d * NN + m0 + tx * 4]       = acc[db][0][dr];
            *(float4*)&Ob[(size_t)d * NN + m0 + 128 + tx * 4] = acc[db][1][dr];
        }
}

// ---------------------------------------------------------------------------
extern "C" void kernel_launch(void* const* d_in, const int* in_sizes, int n_in,
                              void* d_out, int out_size)
{
    const float* inp = (const float*)d_in[0];
    const float* dyn = (const float*)d_in[1];
    const float* wq  = (const float*)d_in[2];
    const float* bq  = (const float*)d_in[3];
    const float* wk  = (const float*)d_in[4];
    const float* bk  = (const float*)d_in[5];
    const float* wv  = (const float*)d_in[6];
    const float* bv  = (const float*)d_in[7];

    float* out  = (float*)d_out;
    float* attn = out + (size_t)BTO * DIM * NN;   // tuple packing: out, then attn

    const int smemB = (CH2 * NN + 1024) * sizeof(float);  // 132 KB
    static bool attr_done = false;
    if (!attr_done) {
        cudaFuncSetAttribute(attn_kernel, cudaFuncAttributeMaxDynamicSharedMemorySize, smemB);
        attr_done = true;
    }

    qkv_kernel<<<448, 256>>>(inp, dyn, wq, bq, wk, bk, wv, bv);
    attn_kernel<<<dim3(32, BTO), 256, smemB>>>(attn);
    av_kernel<<<dim3(4, BTO), 256>>>(attn, out);
}

// round 3
// speedup vs baseline: 1.6798x; 1.0282x over previous
#include <cuda_runtime.h>
#include <cstdint>

#define BS      2
#define TT      8
#define NOBJ    4
#define CH      64
#define CH2     32
#define DIM     64
#define NN      1024
#define BTO     64
#define KBN     16

__device__ float g_Q[BTO * CH2 * NN];   // [b][o][n]
__device__ float g_K[KBN * CH2 * NN];   // [kb][o][m]
__device__ float g_V[KBN * DIM * NN];   // [kb][d][n]

// ---- f32x2 packed helpers (sm_100+) --------------------------------------
__device__ __forceinline__ uint64_t pack2(float x, float y) {
    uint64_t r;
    asm("mov.b64 %0, {%1, %2};" : "=l"(r) : "f"(x), "f"(y));
    return r;
}
__device__ __forceinline__ void fma2(uint64_t& d, uint64_t a, uint64_t b) {
    asm("fma.rn.f32x2 %0, %1, %2, %0;" : "+l"(d) : "l"(a), "l"(b));
}
__device__ __forceinline__ float2 unpack2(uint64_t v) {
    float2 r;
    asm("mov.b64 {%0, %1}, %2;" : "=f"(r.x), "=f"(r.y) : "l"(v));
    return r;
}

// ---------------------------------------------------------------------------
// Kernel 1: QKV projections. 896 blocks, 16 output channels per block.
//   [0,512):   Q  b=id>>3, sub=(id>>2)&1, ntile=id&3
//   [512,640): K  kb=id>>3, sub=(id>>2)&1, ntile=id&3
//   [640,896): V  kb=id>>4, sub=(id>>2)&3, ntile=id&3
// ---------------------------------------------------------------------------
__global__ void __launch_bounds__(256) qkv_kernel(
    const float* __restrict__ inp, const float* __restrict__ dyn,
    const float* __restrict__ wq, const float* __restrict__ bq,
    const float* __restrict__ wk, const float* __restrict__ bk,
    const float* __restrict__ wv, const float* __restrict__ bv)
{
    __shared__ float sw[16 * CH];
    __shared__ float sb[16];

    const int tid = threadIdx.x;
    const int bid = blockIdx.x;

    const float *X, *W, *B;
    float* OUT;
    int ntile;

    if (bid < 512) {
        const int id = bid;
        const int b = id >> 3, sub = (id >> 2) & 1; ntile = id & 3;
        X = dyn + (size_t)b * CH * NN;
        W = wq + sub * 16 * CH; B = bq + sub * 16;
        OUT = g_Q + (size_t)b * CH2 * NN + (size_t)sub * 16 * NN;
    } else if (bid < 640) {
        const int id = bid - 512;
        const int kb = id >> 3, sub = (id >> 2) & 1; ntile = id & 3;
        X = inp + (size_t)kb * CH * NN;
        W = wk + sub * 16 * CH; B = bk + sub * 16;
        OUT = g_K + (size_t)kb * CH2 * NN + (size_t)sub * 16 * NN;
    } else {
        const int id = bid - 640;
        const int kb = id >> 4, sub = (id >> 2) & 3; ntile = id & 3;
        X = inp + (size_t)kb * CH * NN;
        W = wv + sub * 16 * CH; B = bv + sub * 16;
        OUT = g_V + (size_t)kb * DIM * NN + (size_t)sub * 16 * NN;
    }

    for (int i = tid; i < 16 * CH; i += 256) sw[i] = W[i];
    if (tid < 16) sb[tid] = B[tid];
    __syncthreads();

    const int n = ntile * 256 + tid;
    float acc[16];
    #pragma unroll
    for (int o = 0; o < 16; o++) acc[o] = 0.f;

    #pragma unroll
    for (int c0 = 0; c0 < CH; c0 += 8) {
        float x[8];
        #pragma unroll
        for (int j = 0; j < 8; j++) x[j] = X[(c0 + j) * NN + n];
        #pragma unroll
        for (int o = 0; o < 16; o++) {
            const float4 wa = *(const float4*)&sw[o * CH + c0];
            const float4 wb = *(const float4*)&sw[o * CH + c0 + 4];
            acc[o] = fmaf(wa.x, x[0], acc[o]);
            acc[o] = fmaf(wa.y, x[1], acc[o]);
            acc[o] = fmaf(wa.z, x[2], acc[o]);
            acc[o] = fmaf(wa.w, x[3], acc[o]);
            acc[o] = fmaf(wb.x, x[4], acc[o]);
            acc[o] = fmaf(wb.y, x[5], acc[o]);
            acc[o] = fmaf(wb.z, x[6], acc[o]);
            acc[o] = fmaf(wb.w, x[7], acc[o]);
        }
    }
    #pragma unroll
    for (int o = 0; o < 16; o++) OUT[o * NN + n] = acc[o] + sb[o];
}

// ---------------------------------------------------------------------------
// Kernel 2: energy + softmax -> attn. grid=(32,64), block=256.
// K[kb] in smem (128KB); 4 rows/warp in regs, GEMM via fma.rn.f32x2.
// ---------------------------------------------------------------------------
extern __shared__ float s_dyn[];

__global__ void __launch_bounds__(256) attn_kernel(float* __restrict__ attn_out)
{
    float* ks = s_dyn;                 // [32][1024]
    float* qs = s_dyn + CH2 * NN;      // [o][r] 32x32

    const int tid = threadIdx.x;
    const int b   = blockIdx.y;
    const int r0  = blockIdx.x * 32;
    const int t   = b & 7;
    const int bi  = b >> 5;
    const int kb  = bi * TT + t;

    {
        const float4* kg = (const float4*)(g_K + (size_t)kb * CH2 * NN);
        float4* kw = (float4*)ks;
        #pragma unroll
        for (int i = tid; i < CH2 * NN / 4; i += 256) kw[i] = kg[i];
    }
    {
        const float* Qb = g_Q + (size_t)b * CH2 * NN;
        #pragma unroll
        for (int i = tid; i < 1024; i += 256) {
            const int o = i >> 5, r = i & 31;
            qs[i] = Qb[o * NN + r0 + r];
        }
    }
    __syncthreads();

    const int warp = tid >> 5, lane = tid & 31;
    const int rl = warp * 4;

    uint64_t acc[4][16];
    #pragma unroll
    for (int rr = 0; rr < 4; rr++)
        #pragma unroll
        for (int jj = 0; jj < 16; jj++) acc[rr][jj] = 0ull;

    const ulonglong2* ks2 = (const ulonglong2*)ks;
    #pragma unroll 2
    for (int o = 0; o < CH2; o++) {
        uint64_t q2[4];
        #pragma unroll
        for (int rr = 0; rr < 4; rr++) {
            const float qv = qs[o * 32 + rl + rr];
            q2[rr] = pack2(qv, qv);
        }
        const int base = o * 256 + lane;
        #pragma unroll
        for (int j = 0; j < 8; j++) {
            const ulonglong2 kv = ks2[base + 32 * j];
            #pragma unroll
            for (int rr = 0; rr < 4; rr++) {
                fma2(acc[rr][2 * j],     q2[rr], kv.x);
                fma2(acc[rr][2 * j + 1], q2[rr], kv.y);
            }
        }
    }

    #pragma unroll
    for (int rr = 0; rr < 4; rr++) {
        float e[32];
        #pragma unroll
        for (int jj = 0; jj < 16; jj++) {
            const float2 f = unpack2(acc[rr][jj]);
            e[2 * jj] = f.x; e[2 * jj + 1] = f.y;
        }
        float m = -3.4e38f;
        #pragma unroll
        for (int i = 0; i < 32; i++) m = fmaxf(m, e[i]);
        #pragma unroll
        for (int off = 16; off > 0; off >>= 1)
            m = fmaxf(m, __shfl_xor_sync(0xffffffffu, m, off));
        float s = 0.f;
        #pragma unroll
        for (int i = 0; i < 32; i++) { e[i] = __expf(e[i] - m); s += e[i]; }
        #pragma unroll
        for (int off = 16; off > 0; off >>= 1)
            s += __shfl_xor_sync(0xffffffffu, s, off);
        const float inv = 1.f / s;
        const int row = r0 + rl + rr;
        float4* dst = (float4*)(attn_out + ((size_t)b * NN + row) * NN);
        #pragma unroll
        for (int j = 0; j < 8; j++) {
            dst[lane + 32 * j] = make_float4(e[4*j] * inv, e[4*j+1] * inv,
                                             e[4*j+2] * inv, e[4*j+3] * inv);
        }
    }
}

// ---------------------------------------------------------------------------
// Kernel 3: Out[b][d][m] = sum_n V[kb][d][n] * attn[b][m][n]
// grid=(4,64), block=256. 64x256 tile, 8x8 microtile, fma.rn.f32x2 on m-pairs.
// ---------------------------------------------------------------------------
#define PADM 260
#define PADV 68

__global__ void __launch_bounds__(256) av_kernel(
    const float* __restrict__ attn, float* __restrict__ out)
{
    __shared__ float Vs[16 * PADV];   // [k][d]
    __shared__ float As[16 * PADM];   // [k][m]

    const int tid = threadIdx.x;
    const int b   = blockIdx.y;
    const int m0  = blockIdx.x * 256;
    const int t   = b & 7;
    const int bi  = b >> 5;
    const int kb  = bi * TT + t;

    const float* Vg = g_V + (size_t)kb * DIM * NN;
    const float* Ag = attn + ((size_t)b * NN + m0) * NN;

    const int tx = tid & 31, ty = tid >> 5;
    const int lrow = tid >> 2, lnq = tid & 3;

    // acc[db][mb][dr*2+half]: each u64 = 2 adjacent m
    uint64_t acc[2][2][8];
    #pragma unroll
    for (int db = 0; db < 2; db++)
        #pragma unroll
        for (int mb = 0; mb < 2; mb++)
            #pragma unroll
            for (int i = 0; i < 8; i++) acc[db][mb][i] = 0ull;

    for (int c0 = 0; c0 < NN; c0 += 16) {
        {
            const float4 v = *(const float4*)&Vg[(size_t)lrow * NN + c0 + lnq * 4];
            Vs[(lnq * 4 + 0) * PADV + lrow] = v.x;
            Vs[(lnq * 4 + 1) * PADV + lrow] = v.y;
            Vs[(lnq * 4 + 2) * PADV + lrow] = v.z;
            Vs[(lnq * 4 + 3) * PADV + lrow] = v.w;
        }
        #pragma unroll
        for (int p = 0; p < 4; p++) {
            const int m = lrow + 64 * p;
            const float4 a = *(const float4*)&Ag[(size_t)m * NN + c0 + lnq * 4];
            As[(lnq * 4 + 0) * PADM + m] = a.x;
            As[(lnq * 4 + 1) * PADM + m] = a.y;
            As[(lnq * 4 + 2) * PADM + m] = a.z;
            As[(lnq * 4 + 3) * PADM + m] = a.w;
        }
        __syncthreads();

        #pragma unroll
        for (int k = 0; k < 16; k++) {
            const ulonglong2 a0 = *(const ulonglong2*)&As[k * PADM + tx * 4];
            const ulonglong2 a1 = *(const ulonglong2*)&As[k * PADM + 128 + tx * 4];
            const float4 v0 = *(const float4*)&Vs[k * PADV + ty * 4];
            const float4 v1 = *(const float4*)&Vs[k * PADV + 32 + ty * 4];
            uint64_t vp[2][4];
            vp[0][0] = pack2(v0.x, v0.x); vp[0][1] = pack2(v0.y, v0.y);
            vp[0][2] = pack2(v0.z, v0.z); vp[0][3] = pack2(v0.w, v0.w);
            vp[1][0] = pack2(v1.x, v1.x); vp[1][1] = pack2(v1.y, v1.y);
            vp[1][2] = pack2(v1.z, v1.z); vp[1][3] = pack2(v1.w, v1.w);
            #pragma unroll
            for (int db = 0; db < 2; db++)
                #pragma unroll
                for (int dr = 0; dr < 4; dr++) {
                    fma2(acc[db][0][2 * dr],     vp[db][dr], a0.x);
                    fma2(acc[db][0][2 * dr + 1], vp[db][dr], a0.y);
                    fma2(acc[db][1][2 * dr],     vp[db][dr], a1.x);
                    fma2(acc[db][1][2 * dr + 1], vp[db][dr], a1.y);
                }
        }
        __syncthreads();
    }

    float* Ob = out + (size_t)b * DIM * NN;
    #pragma unroll
    for (int db = 0; db < 2; db++)
        #pragma unroll
        for (int dr = 0; dr < 4; dr++) {
            const int d = db * 32 + ty * 4 + dr;
            const float2 l0 = unpack2(acc[db][0][2 * dr]);
            const float2 h0 = unpack2(acc[db][0][2 * dr + 1]);
            const float2 l1 = unpack2(acc[db][1][2 * dr]);
            const float2 h1 = unpack2(acc[db][1][2 * dr + 1]);
            *(float4*)&Ob[(size_t)d * NN + m0 + tx * 4]       = make_float4(l0.x, l0.y, h0.x, h0.y);
            *(float4*)&Ob[(size_t)d * NN + m0 + 128 + tx * 4] = make_float4(l1.x, l1.y, h1.x, h1.y);
        }
}

// ---------------------------------------------------------------------------
extern "C" void kernel_launch(void* const* d_in, const int* in_sizes, int n_in,
                              void* d_out, int out_size)
{
    const float* inp = (const float*)d_in[0];
    const float* dyn = (const float*)d_in[1];
    const float* wq  = (const float*)d_in[2];
    const float* bq  = (const float*)d_in[3];
    const float* wk  = (const float*)d_in[4];
    const float* bk  = (const float*)d_in[5];
    const float* wv  = (const float*)d_in[6];
    const float* bv  = (const float*)d_in[7];

    float* out  = (float*)d_out;
    float* attn = out + (size_t)BTO * DIM * NN;

    const int smemB = (CH2 * NN + 1024) * sizeof(float);
    static bool attr_done = false;
    if (!attr_done) {
        cudaFuncSetAttribute(attn_kernel, cudaFuncAttributeMaxDynamicSharedMemorySize, smemB);
        attr_done = true;
    }

    qkv_kernel<<<896, 256>>>(inp, dyn, wq, bq, wk, bk, wv, bv);
    attn_kernel<<<dim3(32, BTO), 256, smemB>>>(attn);
    av_kernel<<<dim3(4, BTO), 256>>>(attn, out);
}

// round 5
// speedup vs baseline: 2.3090x; 1.3746x over previous
#include <cuda_runtime.h>
#include <cuda_fp16.h>
#include <cstdint>

#define BS      2
#define TT      8
#define NOBJ    4
#define CH      64
#define CH2     32
#define DIM     64
#define NN      1024
#define BTO     64
#define KBN     16

__device__ float  g_Q[BTO * CH2 * NN];   // [b][o][n]
__device__ float  g_K[KBN * CH2 * NN];   // [kb][o][m]
__device__ __half g_V[KBN * DIM * NN];   // [kb][d][n] fp16

__device__ __forceinline__ uint32_t smem_u32(const void* p) {
    uint32_t a;
    asm("{ .reg .u64 t; cvta.to.shared.u64 t, %1; cvt.u32.u64 %0, t; }" : "=r"(a) : "l"(p));
    return a;
}
__device__ __forceinline__ void ldsm_x4(uint32_t& r0, uint32_t& r1, uint32_t& r2,
                                        uint32_t& r3, uint32_t addr) {
    asm volatile("ldmatrix.sync.aligned.m8n8.x4.shared.b16 {%0,%1,%2,%3}, [%4];"
                 : "=r"(r0), "=r"(r1), "=r"(r2), "=r"(r3) : "r"(addr));
}
__device__ __forceinline__ void mma16816(float* d, const uint32_t* a, const uint32_t* b) {
    asm volatile("mma.sync.aligned.m16n8k16.row.col.f32.f16.f16.f32 "
                 "{%0,%1,%2,%3}, {%4,%5,%6,%7}, {%8,%9}, {%0,%1,%2,%3};"
                 : "+f"(d[0]), "+f"(d[1]), "+f"(d[2]), "+f"(d[3])
                 : "r"(a[0]), "r"(a[1]), "r"(a[2]), "r"(a[3]), "r"(b[0]), "r"(b[1]));
}

// ---------------------------------------------------------------------------
// Kernel 1: QKV projections (896 blocks, 16 out channels each).
// V branch writes fp16.
// ---------------------------------------------------------------------------
__global__ void __launch_bounds__(256) qkv_kernel(
    const float* __restrict__ inp, const float* __restrict__ dyn,
    const float* __restrict__ wq, const float* __restrict__ bq,
    const float* __restrict__ wk, const float* __restrict__ bk,
    const float* __restrict__ wv, const float* __restrict__ bv)
{
    __shared__ float sw[16 * CH];
    __shared__ float sb[16];

    const int tid = threadIdx.x;
    const int bid = blockIdx.x;

    const float *X, *W, *B;
    float* OUT = nullptr;
    size_t vbase = 0;
    int ntile, role = 0;

    if (bid < 512) {
        const int id = bid;
        const int b = id >> 3, sub = (id >> 2) & 1; ntile = id & 3;
        X = dyn + (size_t)b * CH * NN;
        W = wq + sub * 16 * CH; B = bq + sub * 16;
        OUT = g_Q + (size_t)b * CH2 * NN + (size_t)sub * 16 * NN;
    } else if (bid < 640) {
        const int id = bid - 512;
        const int kb = id >> 3, sub = (id >> 2) & 1; ntile = id & 3;
        X = inp + (size_t)kb * CH * NN;
        W = wk + sub * 16 * CH; B = bk + sub * 16;
        OUT = g_K + (size_t)kb * CH2 * NN + (size_t)sub * 16 * NN;
    } else {
        const int id = bid - 640;
        const int kb = id >> 4, sub = (id >> 2) & 3; ntile = id & 3;
        X = inp + (size_t)kb * CH * NN;
        W = wv + sub * 16 * CH; B = bv + sub * 16;
        vbase = (size_t)kb * DIM * NN + (size_t)sub * 16 * NN;
        role = 1;
    }

    for (int i = tid; i < 16 * CH; i += 256) sw[i] = W[i];
    if (tid < 16) sb[tid] = B[tid];
    __syncthreads();

    const int n = ntile * 256 + tid;
    float acc[16];
    #pragma unroll
    for (int o = 0; o < 16; o++) acc[o] = 0.f;

    #pragma unroll
    for (int c0 = 0; c0 < CH; c0 += 8) {
        float x[8];
        #pragma unroll
        for (int j = 0; j < 8; j++) x[j] = X[(c0 + j) * NN + n];
        #pragma unroll
        for (int o = 0; o < 16; o++) {
            const float4 wa = *(const float4*)&sw[o * CH + c0];
            const float4 wb = *(const float4*)&sw[o * CH + c0 + 4];
            acc[o] = fmaf(wa.x, x[0], acc[o]);
            acc[o] = fmaf(wa.y, x[1], acc[o]);
            acc[o] = fmaf(wa.z, x[2], acc[o]);
            acc[o] = fmaf(wa.w, x[3], acc[o]);
            acc[o] = fmaf(wb.x, x[4], acc[o]);
            acc[o] = fmaf(wb.y, x[5], acc[o]);
            acc[o] = fmaf(wb.z, x[6], acc[o]);
            acc[o] = fmaf(wb.w, x[7], acc[o]);
        }
    }
    if (role == 0) {
        #pragma unroll
        for (int o = 0; o < 16; o++) OUT[o * NN + n] = acc[o] + sb[o];
    } else {
        #pragma unroll
        for (int o = 0; o < 16; o++)
            g_V[vbase + o * NN + n] = __float2half(acc[o] + sb[o]);
    }
}

// ---------------------------------------------------------------------------
// Kernel 2: energy + softmax -> attn (fp32; 4 rows/warp in regs).
// ---------------------------------------------------------------------------
extern __shared__ float s_dyn[];

__global__ void __launch_bounds__(256) attn_kernel(float* __restrict__ attn_out)
{
    float* ks = s_dyn;
    float* qs = s_dyn + CH2 * NN;

    const int tid = threadIdx.x;
    const int b   = blockIdx.y;
    const int r0  = blockIdx.x * 32;
    const int t   = b & 7;
    const int bi  = b >> 5;
    const int kb  = bi * TT + t;

    {
        const float4* kg = (const float4*)(g_K + (size_t)kb * CH2 * NN);
        float4* kw = (float4*)ks;
        #pragma unroll
        for (int i = tid; i < CH2 * NN / 4; i += 256) kw[i] = kg[i];
    }
    {
        const float* Qb = g_Q + (size_t)b * CH2 * NN;
        #pragma unroll
        for (int i = tid; i < 1024; i += 256) {
            const int o = i >> 5, r = i & 31;
            qs[i] = Qb[o * NN + r0 + r];
        }
    }
    __syncthreads();

    const int warp = tid >> 5, lane = tid & 31;
    const int rl = warp * 4;

    float4 acc[4][8];
    #pragma unroll
    for (int rr = 0; rr < 4; rr++)
        #pragma unroll
        for (int j = 0; j < 8; j++) acc[rr][j] = make_float4(0, 0, 0, 0);

    const float4* ks4 = (const float4*)ks;
    #pragma unroll 2
    for (int o = 0; o < CH2; o++) {
        float q[4];
        #pragma unroll
        for (int rr = 0; rr < 4; rr++) q[rr] = qs[o * 32 + rl + rr];
        const int base = o * 256 + lane;
        #pragma unroll
        for (int j = 0; j < 8; j++) {
            const float4 kv = ks4[base + 32 * j];
            #pragma unroll
            for (int rr = 0; rr < 4; rr++) {
                acc[rr][j].x = fmaf(q[rr], kv.x, acc[rr][j].x);
                acc[rr][j].y = fmaf(q[rr], kv.y, acc[rr][j].y);
                acc[rr][j].z = fmaf(q[rr], kv.z, acc[rr][j].z);
                acc[rr][j].w = fmaf(q[rr], kv.w, acc[rr][j].w);
            }
        }
    }

    #pragma unroll
    for (int rr = 0; rr < 4; rr++) {
        float m = -3.4e38f;
        #pragma unroll
        for (int j = 0; j < 8; j++)
            m = fmaxf(m, fmaxf(fmaxf(acc[rr][j].x, acc[rr][j].y),
                               fmaxf(acc[rr][j].z, acc[rr][j].w)));
        #pragma unroll
        for (int off = 16; off > 0; off >>= 1)
            m = fmaxf(m, __shfl_xor_sync(0xffffffffu, m, off));
        float s = 0.f;
        #pragma unroll
        for (int j = 0; j < 8; j++) {
            acc[rr][j].x = __expf(acc[rr][j].x - m);
            acc[rr][j].y = __expf(acc[rr][j].y - m);
            acc[rr][j].z = __expf(acc[rr][j].z - m);
            acc[rr][j].w = __expf(acc[rr][j].w - m);
            s += acc[rr][j].x + acc[rr][j].y + acc[rr][j].z + acc[rr][j].w;
        }
        #pragma unroll
        for (int off = 16; off > 0; off >>= 1)
            s += __shfl_xor_sync(0xffffffffu, s, off);
        const float inv = 1.f / s;
        const int row = r0 + rl + rr;
        float4* dst = (float4*)(attn_out + ((size_t)b * NN + row) * NN);
        #pragma unroll
        for (int j = 0; j < 8; j++) {
            float4 p = acc[rr][j];
            p.x *= inv; p.y *= inv; p.z *= inv; p.w *= inv;
            dst[lane + 32 * j] = p;
        }
    }
}

// ---------------------------------------------------------------------------
// Kernel 3 (HMMA): Out[b][d][m] = sum_n attn[m][n] * V[d][n], fp16 mma.sync.
// grid=(8 mtiles, 64 b), block=256 (8 warps, each m16 x d64).
// A = attn tile [128m x 64n] fp32->fp16 in smem (stride 72 halfs, ldmatrix
// conflict-free); B = V [64d x 64n] fp16. 16 n-chunks, register prefetch.
// ---------------------------------------------------------------------------
#define PADA 72
#define PADV 72
#define PADO 132
#define AV_SMEM 33792   // max(As+Vs = 27648, Os = 64*132*4 = 33792)

extern __shared__ __align__(16) unsigned char avsm[];

__global__ void __launch_bounds__(256) av_hmma_kernel(
    const float* __restrict__ attn, float* __restrict__ out)
{
    __half* As = (__half*)avsm;                        // [128][PADA]
    __half* Vs = (__half*)(avsm + 128 * PADA * 2);     // [64][PADV]
    float*  Os = (float*)avsm;                         // epilogue [64][PADO]

    const int tid = threadIdx.x;
    const int wid = tid >> 5, lane = tid & 31;
    const int b   = blockIdx.y;
    const int m0  = blockIdx.x * 128;
    const int kb  = (b >> 5) * TT + (b & 7);

    const float*  Ag = attn + ((size_t)b * NN + m0) * NN;
    const __half* Vg = g_V + (size_t)kb * DIM * NN;

    // loader mappings
    const int arow = tid >> 1, ahalf = tid & 1;   // A: 2 thr/row, 32 floats each
    const int vrow = tid >> 2, vseg = tid & 3;    // V: 4 thr/row, 16 halfs each

    // ldmatrix per-warp base addresses (bytes)
    const uint32_t uAs = smem_u32(As), uVs = smem_u32(Vs);
    const uint32_t aBase = uAs + (uint32_t)(((wid * 16) + (lane & 15)) * PADA + (lane >> 4) * 8) * 2;
    const uint32_t bBase = uVs + (uint32_t)(((lane & 7) + ((lane >> 4) & 1) * 8) * PADV
                                            + ((lane >> 3) & 1) * 8) * 2;

    float acc[32];
    #pragma unroll
    for (int i = 0; i < 32; i++) acc[i] = 0.f;

    float4 areg[8];
    uint4  vreg[2];

    // ---- prologue: load + store chunk 0 ----
    #pragma unroll
    for (int j = 0; j < 8; j++)
        areg[j] = *(const float4*)&Ag[(size_t)arow * NN + (ahalf * 8 + j) * 4];
    {
        const __half* vp = Vg + (size_t)vrow * NN + vseg * 16;
        vreg[0] = *(const uint4*)vp; vreg[1] = *(const uint4*)(vp + 8);
    }
    #pragma unroll
    for (int j = 0; j < 8; j++) {
        __half2 h0 = __float22half2_rn(make_float2(areg[j].x, areg[j].y));
        __half2 h1 = __float22half2_rn(make_float2(areg[j].z, areg[j].w));
        *(uint2*)&As[arow * PADA + ahalf * 32 + j * 4] =
            make_uint2(*(uint32_t*)&h0, *(uint32_t*)&h1);
    }
    *(uint4*)&Vs[vrow * PADV + vseg * 16]     = vreg[0];
    *(uint4*)&Vs[vrow * PADV + vseg * 16 + 8] = vreg[1];
    __syncthreads();

    // ---- main loop over 16 n-chunks of 64 ----
    for (int ck = 0; ck < 16; ck++) {
        if (ck < 15) {
            const int c0 = (ck + 1) * 64;
            #pragma unroll
            for (int j = 0; j < 8; j++)
                areg[j] = *(const float4*)&Ag[(size_t)arow * NN + c0 + (ahalf * 8 + j) * 4];
            const __half* vp = Vg + (size_t)vrow * NN + c0 + vseg * 16;
            vreg[0] = *(const uint4*)vp; vreg[1] = *(const uint4*)(vp + 8);
        }

        #pragma unroll
        for (int kk = 0; kk < 4; kk++) {
            uint32_t a[4];
            ldsm_x4(a[0], a[1], a[2], a[3], aBase + kk * 32);
            #pragma unroll
            for (int p = 0; p < 4; p++) {
                uint32_t bf[4];
                ldsm_x4(bf[0], bf[1], bf[2], bf[3], bBase + p * (16 * PADV * 2) + kk * 32);
                mma16816(acc + (2 * p) * 4,     a, bf);
                mma16816(acc + (2 * p + 1) * 4, a, bf + 2);
            }
        }
        __syncthreads();

        if (ck < 15) {
            #pragma unroll
            for (int j = 0; j < 8; j++) {
                __half2 h0 = __float22half2_rn(make_float2(areg[j].x, areg[j].y));
                __half2 h1 = __float22half2_rn(make_float2(areg[j].z, areg[j].w));
                *(uint2*)&As[arow * PADA + ahalf * 32 + j * 4] =
                    make_uint2(*(uint32_t*)&h0, *(uint32_t*)&h1);
            }
            *(uint4*)&Vs[vrow * PADV + vseg * 16]     = vreg[0];
            *(uint4*)&Vs[vrow * PADV + vseg * 16 + 8] = vreg[1];
            __syncthreads();
        }
    }

    // ---- epilogue: acc -> Os[d][m] -> coalesced out[b][d][m0+...] ----
    {
        const int mr = wid * 16 + (lane >> 2);
        const int cc = (lane & 3) * 2;
        #pragma unroll
        for (int dt = 0; dt < 8; dt++) {
            const int d = dt * 8 + cc;
            Os[d * PADO + mr]           = acc[dt * 4 + 0];
            Os[(d + 1) * PADO + mr]     = acc[dt * 4 + 1];
            Os[d * PADO + mr + 8]       = acc[dt * 4 + 2];
            Os[(d + 1) * PADO + mr + 8] = acc[dt * 4 + 3];
        }
    }
    __syncthreads();
    {
        float* Ob = out + (size_t)b * DIM * NN + m0;
        #pragma unroll
        for (int i = 0; i < 8; i++) {
            const int d = wid * 8 + i;
            const float4 v = *(const float4*)&Os[d * PADO + lane * 4];
            *(float4*)&Ob[(size_t)d * NN + lane * 4] = v;
        }
    }
}

// ---------------------------------------------------------------------------
extern "C" void kernel_launch(void* const* d_in, const int* in_sizes, int n_in,
                              void* d_out, int out_size)
{
    const float* inp = (const float*)d_in[0];
    const float* dyn = (const float*)d_in[1];
    const float* wq  = (const float*)d_in[2];
    const float* bq  = (const float*)d_in[3];
    const float* wk  = (const float*)d_in[4];
    const float* bk  = (const float*)d_in[5];
    const float* wv  = (const float*)d_in[6];
    const float* bv  = (const float*)d_in[7];

    float* out  = (float*)d_out;
    float* attn = out + (size_t)BTO * DIM * NN;

    const int smemB = (CH2 * NN + 1024) * sizeof(float);
    static bool attr_done = false;
    if (!attr_done) {
        cudaFuncSetAttribute(attn_kernel, cudaFuncAttributeMaxDynamicSharedMemorySize, smemB);
        cudaFuncSetAttribute(av_hmma_kernel, cudaFuncAttributeMaxDynamicSharedMemorySize, AV_SMEM);
        attr_done = true;
    }

    qkv_kernel<<<896, 256>>>(inp, dyn, wq, bq, wk, bk, wv, bv);
    attn_kernel<<<dim3(32, BTO), 256, smemB>>>(attn);
    av_hmma_kernel<<<dim3(8, BTO), 256, AV_SMEM>>>(attn, out);
}

// round 6
// speedup vs baseline: 2.6641x; 1.1538x over previous
#include <cuda_runtime.h>
#include <cuda_fp16.h>
#include <cstdint>

#define BS      2
#define TT      8
#define NOBJ    4
#define CH      64
#define CH2     32
#define DIM     64
#define NN      1024
#define BTO     64
#define KBN     16

__device__ float  g_Q[BTO * CH2 * NN];   // [b][o][n]
__device__ float  g_K[KBN * CH2 * NN];   // [kb][o][m]
__device__ __half g_V[KBN * DIM * NN];   // [kb][d][n] fp16

__device__ __forceinline__ uint32_t smem_u32(const void* p) {
    uint32_t a;
    asm("{ .reg .u64 t; cvta.to.shared.u64 t, %1; cvt.u32.u64 %0, t; }" : "=r"(a) : "l"(p));
    return a;
}
__device__ __forceinline__ void ldsm_x4(uint32_t* r, uint32_t addr) {
    asm volatile("ldmatrix.sync.aligned.m8n8.x4.shared.b16 {%0,%1,%2,%3}, [%4];"
                 : "=r"(r[0]), "=r"(r[1]), "=r"(r[2]), "=r"(r[3]) : "r"(addr));
}
__device__ __forceinline__ void mma16816(float* d, const uint32_t* a, const uint32_t* b) {
    asm volatile("mma.sync.aligned.m16n8k16.row.col.f32.f16.f16.f32 "
                 "{%0,%1,%2,%3}, {%4,%5,%6,%7}, {%8,%9}, {%0,%1,%2,%3};"
                 : "+f"(d[0]), "+f"(d[1]), "+f"(d[2]), "+f"(d[3])
                 : "r"(a[0]), "r"(a[1]), "r"(a[2]), "r"(a[3]), "r"(b[0]), "r"(b[1]));
}

// ---------------------------------------------------------------------------
// Kernel 1: QKV projections (896 blocks, 16 out channels each). V -> fp16.
// ---------------------------------------------------------------------------
__global__ void __launch_bounds__(256) qkv_kernel(
    const float* __restrict__ inp, const float* __restrict__ dyn,
    const float* __restrict__ wq, const float* __restrict__ bq,
    const float* __restrict__ wk, const float* __restrict__ bk,
    const float* __restrict__ wv, const float* __restrict__ bv)
{
    __shared__ float sw[16 * CH];
    __shared__ float sb[16];

    const int tid = threadIdx.x;
    const int bid = blockIdx.x;

    const float *X, *W, *B;
    float* OUT = nullptr;
    size_t vbase = 0;
    int ntile, role = 0;

    if (bid < 512) {
        const int id = bid;
        const int b = id >> 3, sub = (id >> 2) & 1; ntile = id & 3;
        X = dyn + (size_t)b * CH * NN;
        W = wq + sub * 16 * CH; B = bq + sub * 16;
        OUT = g_Q + (size_t)b * CH2 * NN + (size_t)sub * 16 * NN;
    } else if (bid < 640) {
        const int id = bid - 512;
        const int kb = id >> 3, sub = (id >> 2) & 1; ntile = id & 3;
        X = inp + (size_t)kb * CH * NN;
        W = wk + sub * 16 * CH; B = bk + sub * 16;
        OUT = g_K + (size_t)kb * CH2 * NN + (size_t)sub * 16 * NN;
    } else {
        const int id = bid - 640;
        const int kb = id >> 4, sub = (id >> 2) & 3; ntile = id & 3;
        X = inp + (size_t)kb * CH * NN;
        W = wv + sub * 16 * CH; B = bv + sub * 16;
        vbase = (size_t)kb * DIM * NN + (size_t)sub * 16 * NN;
        role = 1;
    }

    for (int i = tid; i < 16 * CH; i += 256) sw[i] = W[i];
    if (tid < 16) sb[tid] = B[tid];
    __syncthreads();

    const int n = ntile * 256 + tid;
    float acc[16];
    #pragma unroll
    for (int o = 0; o < 16; o++) acc[o] = 0.f;

    #pragma unroll
    for (int c0 = 0; c0 < CH; c0 += 8) {
        float x[8];
        #pragma unroll
        for (int j = 0; j < 8; j++) x[j] = X[(c0 + j) * NN + n];
        #pragma unroll
        for (int o = 0; o < 16; o++) {
            const float4 wa = *(const float4*)&sw[o * CH + c0];
            const float4 wb = *(const float4*)&sw[o * CH + c0 + 4];
            acc[o] = fmaf(wa.x, x[0], acc[o]);
            acc[o] = fmaf(wa.y, x[1], acc[o]);
            acc[o] = fmaf(wa.z, x[2], acc[o]);
            acc[o] = fmaf(wa.w, x[3], acc[o]);
            acc[o] = fmaf(wb.x, x[4], acc[o]);
            acc[o] = fmaf(wb.y, x[5], acc[o]);
            acc[o] = fmaf(wb.z, x[6], acc[o]);
            acc[o] = fmaf(wb.w, x[7], acc[o]);
        }
    }
    if (role == 0) {
        #pragma unroll
        for (int o = 0; o < 16; o++) OUT[o * NN + n] = acc[o] + sb[o];
    } else {
        #pragma unroll
        for (int o = 0; o < 16; o++)
            g_V[vbase + o * NN + n] = __float2half(acc[o] + sb[o]);
    }
}

// ---------------------------------------------------------------------------
// Fused kernel: energy (HMMA, Q hi/lo split) + softmax + AV (HMMA).
// grid=(32 mtiles, 64 b), block=256 (8 warps: mh=wid>>2, nq/dq=wid&3).
// ---------------------------------------------------------------------------
#define KSS 40     // K smem row stride (halfs)
#define QSS 40
#define PSS 1032
#define VSS 136
#define OSS 36

#define OFF_KS 0
#define OFF_QH 81920
#define OFF_QL 84480
#define OFF_P  87040
#define OFF_VS 153088
#define OFF_RM 170496
#define OFF_RS 171008
#define FUSED_SMEM 171520
#define OFF_OS 0              // Os overlaps Ks (phase 1 done)

extern __shared__ __align__(16) unsigned char fsm[];

__global__ void __launch_bounds__(256) fused_kernel(
    float* __restrict__ attn_out, float* __restrict__ out)
{
    __half* Ks  = (__half*)(fsm + OFF_KS);
    __half* Qh  = (__half*)(fsm + OFF_QH);
    __half* Ql  = (__half*)(fsm + OFF_QL);
    __half* P   = (__half*)(fsm + OFF_P);
    __half* Vs  = (__half*)(fsm + OFF_VS);
    float* redM = (float*)(fsm + OFF_RM);
    float* redS = (float*)(fsm + OFF_RS);
    float* Os   = (float*)(fsm + OFF_OS);

    const int tid  = threadIdx.x;
    const int wid  = tid >> 5, lane = tid & 31;
    const int b    = blockIdx.y;
    const int m0   = blockIdx.x * 32;
    const int kb   = (b >> 5) * TT + (b & 7);
    const int mh   = wid >> 2, nq = wid & 3;

    // ---- load K[kb] transposed to fp16 Ks[m][o] ----
    const float* Kg = g_K + (size_t)kb * CH2 * NN;
    #pragma unroll
    for (int i = 0; i < 64; i++) {
        const int idx = i * 256 + tid;             // 16384 half2 slots
        const int op = idx >> 10, m = idx & 1023;
        const float k0 = Kg[(2 * op) * NN + m];
        const float k1 = Kg[(2 * op + 1) * NN + m];
        *(__half2*)&Ks[m * KSS + 2 * op] = __floats2half2_rn(k0, k1);
    }
    // ---- load Q tile [32 r][32 o] hi/lo ----
    const float* Qg = g_Q + (size_t)b * CH2 * NN;
    #pragma unroll
    for (int i = 0; i < 4; i++) {
        const int idx = i * 256 + tid;
        const int o = idx >> 5, r = idx & 31;
        const float q = Qg[o * NN + m0 + r];
        const __half qh = __float2half(q);
        Qh[r * QSS + o] = qh;
        Ql[r * QSS + o] = __float2half(q - __half2float(qh));
    }
    __syncthreads();

    // ---- phase 1: energy MMA (32m x 1024n x 32k), Qh*K + Ql*K ----
    const uint32_t aoff = (uint32_t)(((mh * 16 + (lane & 15)) * QSS + (lane >> 4) * 8) * 2);
    uint32_t ah0[4], ah1[4], al0[4], al1[4];
    ldsm_x4(ah0, smem_u32(Qh) + aoff);
    ldsm_x4(ah1, smem_u32(Qh) + aoff + 32);
    ldsm_x4(al0, smem_u32(Ql) + aoff);
    ldsm_x4(al1, smem_u32(Ql) + aoff + 32);

    const uint32_t brow = (lane & 7) + ((lane >> 4) & 1) * 8;
    const uint32_t bcol = ((lane >> 3) & 1) * 8;
    uint32_t bbase = smem_u32(Ks) + (uint32_t)(((nq * 256 + brow) * KSS + bcol) * 2);

    float acc[16][8];
    #pragma unroll
    for (int nt = 0; nt < 16; nt++)
        #pragma unroll
        for (int c = 0; c < 8; c++) acc[nt][c] = 0.f;

    #pragma unroll
    for (int nt = 0; nt < 16; nt++) {
        uint32_t b0[4], b1[4];
        ldsm_x4(b0, bbase);
        ldsm_x4(b1, bbase + 32);
        mma16816(acc[nt] + 0, ah0, b0 + 0); mma16816(acc[nt] + 4, ah0, b0 + 2);
        mma16816(acc[nt] + 0, ah1, b1 + 0); mma16816(acc[nt] + 4, ah1, b1 + 2);
        mma16816(acc[nt] + 0, al0, b0 + 0); mma16816(acc[nt] + 4, al0, b0 + 2);
        mma16816(acc[nt] + 0, al1, b1 + 0); mma16816(acc[nt] + 4, al1, b1 + 2);
        bbase += 16 * KSS * 2;
    }

    // ---- phase 2: softmax (rows rowA=mh*16+ra, rowB=rowA+8) ----
    const int ra = lane >> 2;
    const int rowA = mh * 16 + ra, rowB = rowA + 8;

    float mA = -3.4e38f, mB = -3.4e38f;
    #pragma unroll
    for (int nt = 0; nt < 16; nt++) {
        mA = fmaxf(mA, fmaxf(fmaxf(acc[nt][0], acc[nt][1]), fmaxf(acc[nt][4], acc[nt][5])));
        mB = fmaxf(mB, fmaxf(fmaxf(acc[nt][2], acc[nt][3]), fmaxf(acc[nt][6], acc[nt][7])));
    }
    mA = fmaxf(mA, __shfl_xor_sync(0xffffffffu, mA, 1));
    mA = fmaxf(mA, __shfl_xor_sync(0xffffffffu, mA, 2));
    mB = fmaxf(mB, __shfl_xor_sync(0xffffffffu, mB, 1));
    mB = fmaxf(mB, __shfl_xor_sync(0xffffffffu, mB, 2));
    if ((lane & 3) == 0) { redM[nq * 32 + rowA] = mA; redM[nq * 32 + rowB] = mB; }
    __syncthreads();
    mA = fmaxf(fmaxf(redM[rowA], redM[32 + rowA]), fmaxf(redM[64 + rowA], redM[96 + rowA]));
    mB = fmaxf(fmaxf(redM[rowB], redM[32 + rowB]), fmaxf(redM[64 + rowB], redM[96 + rowB]));

    float sA = 0.f, sB = 0.f;
    #pragma unroll
    for (int nt = 0; nt < 16; nt++) {
        acc[nt][0] = __expf(acc[nt][0] - mA); acc[nt][1] = __expf(acc[nt][1] - mA);
        acc[nt][4] = __expf(acc[nt][4] - mA); acc[nt][5] = __expf(acc[nt][5] - mA);
        acc[nt][2] = __expf(acc[nt][2] - mB); acc[nt][3] = __expf(acc[nt][3] - mB);
        acc[nt][6] = __expf(acc[nt][6] - mB); acc[nt][7] = __expf(acc[nt][7] - mB);
        sA += acc[nt][0] + acc[nt][1] + acc[nt][4] + acc[nt][5];
        sB += acc[nt][2] + acc[nt][3] + acc[nt][6] + acc[nt][7];
    }
    sA += __shfl_xor_sync(0xffffffffu, sA, 1);
    sA += __shfl_xor_sync(0xffffffffu, sA, 2);
    sB += __shfl_xor_sync(0xffffffffu, sB, 1);
    sB += __shfl_xor_sync(0xffffffffu, sB, 2);
    if ((lane & 3) == 0) { redS[nq * 32 + rowA] = sA; redS[nq * 32 + rowB] = sB; }
    __syncthreads();
    sA = redS[rowA] + redS[32 + rowA] + redS[64 + rowA] + redS[96 + rowA];
    sB = redS[rowB] + redS[32 + rowB] + redS[64 + rowB] + redS[96 + rowB];
    const float invA = 1.f / sA, invB = 1.f / sB;

    // ---- store probs: gmem (output) + smem P (fp16) ----
    float* arow0 = attn_out + ((size_t)b * NN + m0 + rowA) * NN;
    float* arow1 = attn_out + ((size_t)b * NN + m0 + rowB) * NN;
    #pragma unroll
    for (int nt = 0; nt < 16; nt++) {
        const int c0 = nq * 256 + nt * 16 + (lane & 3) * 2;
        const float p00 = acc[nt][0] * invA, p01 = acc[nt][1] * invA;
        const float p10 = acc[nt][4] * invA, p11 = acc[nt][5] * invA;
        const float p20 = acc[nt][2] * invB, p21 = acc[nt][3] * invB;
        const float p30 = acc[nt][6] * invB, p31 = acc[nt][7] * invB;
        *(float2*)&arow0[c0]     = make_float2(p00, p01);
        *(float2*)&arow0[c0 + 8] = make_float2(p10, p11);
        *(float2*)&arow1[c0]     = make_float2(p20, p21);
        *(float2*)&arow1[c0 + 8] = make_float2(p30, p31);
        *(__half2*)&P[rowA * PSS + c0]     = __floats2half2_rn(p00, p01);
        *(__half2*)&P[rowA * PSS + c0 + 8] = __floats2half2_rn(p10, p11);
        *(__half2*)&P[rowB * PSS + c0]     = __floats2half2_rn(p20, p21);
        *(__half2*)&P[rowB * PSS + c0 + 8] = __floats2half2_rn(p30, p31);
    }
    __syncthreads();

    // ---- phase 3: out = P @ V^T (32m x 64d x 1024k), V chunks of 128 ----
    const int dq = nq;
    const uint32_t aPoff = smem_u32(P) +
        (uint32_t)(((mh * 16 + (lane & 15)) * PSS + (lane >> 4) * 8) * 2);
    const uint32_t bVoff = smem_u32(Vs) +
        (uint32_t)(((dq * 16 + brow) * VSS + bcol) * 2);

    float acc2[8];
    #pragma unroll
    for (int i = 0; i < 8; i++) acc2[i] = 0.f;

    const __half* Vg = g_V + (size_t)kb * DIM * NN;
    const int vd = tid >> 2, vseg = tid & 3;

    for (int kc = 0; kc < 8; kc++) {
        {
            const __half* vp = Vg + (size_t)vd * NN + kc * 128 + vseg * 32;
            const uint4 v0 = *(const uint4*)vp;
            const uint4 v1 = *(const uint4*)(vp + 8);
            const uint4 v2 = *(const uint4*)(vp + 16);
            const uint4 v3 = *(const uint4*)(vp + 24);
            *(uint4*)&Vs[vd * VSS + vseg * 32]      = v0;
            *(uint4*)&Vs[vd * VSS + vseg * 32 + 8]  = v1;
            *(uint4*)&Vs[vd * VSS + vseg * 32 + 16] = v2;
            *(uint4*)&Vs[vd * VSS + vseg * 32 + 24] = v3;
        }
        __syncthreads();
        #pragma unroll
        for (int ks = 0; ks < 8; ks++) {
            uint32_t a[4], bf[4];
            ldsm_x4(a, aPoff + (uint32_t)((kc * 128 + ks * 16) * 2));
            ldsm_x4(bf, bVoff + (uint32_t)(ks * 32));
            mma16816(acc2 + 0, a, bf);
            mma16816(acc2 + 4, a, bf + 2);
        }
        __syncthreads();
    }

    // ---- epilogue: transpose via Os, coalesced out[b][d][m0+..] ----
    #pragma unroll
    for (int sub = 0; sub < 2; sub++) {
        const int d = dq * 16 + sub * 8 + (lane & 3) * 2;
        const int m = mh * 16 + ra;
        Os[d * OSS + m]           = acc2[sub * 4 + 0];
        Os[(d + 1) * OSS + m]     = acc2[sub * 4 + 1];
        Os[d * OSS + m + 8]       = acc2[sub * 4 + 2];
        Os[(d + 1) * OSS + m + 8] = acc2[sub * 4 + 3];
    }
    __syncthreads();
    {
        const int d = tid >> 2, ms = (tid & 3) * 8;
        float* Ob = out + (size_t)b * DIM * NN + (size_t)d * NN + m0 + ms;
        const float4 v0 = *(const float4*)&Os[d * OSS + ms];
        const float4 v1 = *(const float4*)&Os[d * OSS + ms + 4];
        *(float4*)&Ob[0] = v0;
        *(float4*)&Ob[4] = v1;
    }
}

// ---------------------------------------------------------------------------
extern "C" void kernel_launch(void* const* d_in, const int* in_sizes, int n_in,
                              void* d_out, int out_size)
{
    const float* inp = (const float*)d_in[0];
    const float* dyn = (const float*)d_in[1];
    const float* wq  = (const float*)d_in[2];
    const float* bq  = (const float*)d_in[3];
    const float* wk  = (const float*)d_in[4];
    const float* bk  = (const float*)d_in[5];
    const float* wv  = (const float*)d_in[6];
    const float* bv  = (const float*)d_in[7];

    float* out  = (float*)d_out;
    float* attn = out + (size_t)BTO * DIM * NN;

    static bool attr_done = false;
    if (!attr_done) {
        cudaFuncSetAttribute(fused_kernel, cudaFuncAttributeMaxDynamicSharedMemorySize, FUSED_SMEM);
        attr_done = true;
    }

    qkv_kernel<<<896, 256>>>(inp, dyn, wq, bq, wk, bk, wv, bv);
    fused_kernel<<<dim3(32, BTO), 256, FUSED_SMEM>>>(attn, out);
}